// round 6
// baseline (speedup 1.0000x reference)
#include <cuda_runtime.h>

// B=64, T=1024, J=32 (fixed by the reference's setup_inputs)
#define B_ 64
#define T_ 1024
#define J_ 32

// Scratch: per-(b,t) root trajectory (x,z only) — 64*1024 float2 = 512 KB
__device__ float2 d_traj[B_ * T_];

// Rotate point p by quaternion (w, x, y, z): p' = p + 2w(v x p) + 2 v x (v x p)
__device__ __forceinline__ void quat_rotate(
    float w, float x, float y, float z,
    float px, float py, float pz,
    float& rx, float& ry, float& rz)
{
    float tx = 2.0f * (y * pz - z * py);
    float ty = 2.0f * (z * px - x * pz);
    float tz = 2.0f * (x * py - y * px);
    rx = px + w * tx + (y * tz - z * ty);
    ry = py + w * ty + (z * tx - x * tz);
    rz = pz + w * tz + (x * ty - y * tx);
}

// One block per batch b; 1024 threads = T time steps.
__global__ void traj_kernel(const float* __restrict__ glb_pos,
                            const float* __restrict__ glb_vel,
                            const float* __restrict__ root_rot)
{
    const int b = blockIdx.x;
    const int t = threadIdx.x;

    // conj(root[b,t])
    const float4 q4 = __ldg(reinterpret_cast<const float4*>(root_rot) + (size_t)b * T_ + t);
    const float w = q4.x, qx = -q4.y, qy = -q4.z, qz = -q4.w;

    // vel_rot[b,t,0] (x,z) for t < T-1
    float ex = 0.0f, ez = 0.0f;
    if (t < T_ - 1) {
        // joint-0 velocity: 12 bytes at a 384-byte stride, 16B-aligned, and
        // 31 joints of data follow it -> a 16B vector load is safe & in-bounds.
        const size_t fidx = (((size_t)b * (T_ - 1) + t) * J_) * 3;
        const float4 v4 = __ldg(reinterpret_cast<const float4*>(glb_vel + fidx));
        float rx, ry, rz;
        quat_rotate(w, qx, qy, qz, v4.x, v4.y, v4.z, rx, ry, rz);
        ex = rx; ez = rz;
    }

    // --- exclusive block scan of (ex, ez) over the 1024 threads ---
    const int lane = t & 31, warp = t >> 5;
    float ix = ex, iz = ez;  // warp-inclusive
    #pragma unroll
    for (int o = 1; o < 32; o <<= 1) {
        float sx = __shfl_up_sync(0xFFFFFFFFu, ix, o);
        float sz = __shfl_up_sync(0xFFFFFFFFu, iz, o);
        if (lane >= o) { ix += sx; iz += sz; }
    }

    __shared__ float wsx[32], wsz[32];
    __shared__ float2 base_sh;
    if (lane == 31) { wsx[warp] = ix; wsz[warp] = iz; }

    if (t == 0) {
        // base = rotate(conj(root[b,0]), glb_pos[b,0,0]); thread 0 holds root[b,0]
        const float4 p4 = __ldg(reinterpret_cast<const float4*>(glb_pos + (size_t)b * T_ * J_ * 3));
        float bx, by, bz;
        quat_rotate(w, qx, qy, qz, p4.x, p4.y, p4.z, bx, by, bz);
        base_sh = make_float2(bx, bz);
    }
    __syncthreads();

    if (warp == 0) {
        float sx = wsx[lane], sz = wsz[lane];
        #pragma unroll
        for (int o = 1; o < 32; o <<= 1) {
            float ax = __shfl_up_sync(0xFFFFFFFFu, sx, o);
            float az = __shfl_up_sync(0xFFFFFFFFu, sz, o);
            if (lane >= o) { sx += ax; sz += az; }
        }
        wsx[lane] = sx; wsz[lane] = sz;
    }
    __syncthreads();

    float prefx = (ix - ex) + (warp > 0 ? wsx[warp - 1] : 0.0f);
    float prefz = (iz - ez) + (warp > 0 ? wsz[warp - 1] : 0.0f);

    d_traj[(size_t)b * T_ + t] = make_float2(base_sh.x + prefx, base_sh.y + prefz);
}

// 4 points per thread, all loads/stores 16B-vectorized.
// Thread u handles global point indices 4u..4u+3; since 4 | J, all 4 points
// share one (b,t) = u>>3. Per warp: 9 LDG + 7 STG (vs 40 mem insts for the
// scalar version) moving identical bytes.
__global__ void apply_kernel(const float4* __restrict__ glb_pos4,
                             const float4* __restrict__ glb_rot4,
                             const float4* __restrict__ root_rot4,
                             float4* __restrict__ pos_out4,
                             float4* __restrict__ rot_out4)
{
    const size_t u = (size_t)blockIdx.x * blockDim.x + threadIdx.x;
    const size_t NU = (size_t)B_ * T_ * J_ / 4;  // threads
    if (u >= NU) return;

    const size_t bt = u >> 3;  // (4u)>>5

    const float4 q4 = __ldg(root_rot4 + bt);
    const float w = q4.x, qx = -q4.y, qy = -q4.z, qz = -q4.w;  // conj(root)

    // Rotation matrix of conj(root) (unit quaternion)
    const float xx = qx * qx, yy = qy * qy, zz = qz * qz;
    const float xy = qx * qy, xz = qx * qz, yz = qy * qz;
    const float wx = w * qx, wy = w * qy, wz = w * qz;
    const float R00 = 1.0f - 2.0f * (yy + zz);
    const float R01 = 2.0f * (xy - wz);
    const float R02 = 2.0f * (xz + wy);
    const float R10 = 2.0f * (xy + wz);
    const float R11 = 1.0f - 2.0f * (xx + zz);
    const float R12 = 2.0f * (yz - wx);
    const float R20 = 2.0f * (xz - wy);
    const float R21 = 2.0f * (yz + wx);
    const float R22 = 1.0f - 2.0f * (xx + yy);

    const float2 tr = __ldg(&d_traj[bt]);

    // --- pos path: 12 floats = 4 points in 3 float4s ---
    const float4 a = __ldg(glb_pos4 + u * 3 + 0);  // p0x p0y p0z p1x
    const float4 bq = __ldg(glb_pos4 + u * 3 + 1); // p1y p1z p2x p2y
    const float4 c = __ldg(glb_pos4 + u * 3 + 2);  // p2z p3x p3y p3z

    // p0
    float o0x = R00 * a.x + R01 * a.y + R02 * a.z;
    float o0y = R10 * a.x + R11 * a.y + R12 * a.z;
    float o0z = R20 * a.x + R21 * a.y + R22 * a.z;
    // p1
    float o1x = R00 * a.w + R01 * bq.x + R02 * bq.y;
    float o1y = R10 * a.w + R11 * bq.x + R12 * bq.y;
    float o1z = R20 * a.w + R21 * bq.x + R22 * bq.y;
    // p2
    float o2x = R00 * bq.z + R01 * bq.w + R02 * c.x;
    float o2y = R10 * bq.z + R11 * bq.w + R12 * c.x;
    float o2z = R20 * bq.z + R21 * bq.w + R22 * c.x;
    // p3
    float o3x = R00 * c.y + R01 * c.z + R02 * c.w;
    float o3y = R10 * c.y + R11 * c.z + R12 * c.w;
    float o3z = R20 * c.y + R21 * c.z + R22 * c.w;

    pos_out4[u * 3 + 0] = make_float4(o0x + tr.x, o0y, o0z + tr.y, o1x + tr.x);
    pos_out4[u * 3 + 1] = make_float4(o1y, o1z + tr.y, o2x + tr.x, o2y);
    pos_out4[u * 3 + 2] = make_float4(o2z + tr.y, o3x + tr.x, o3y, o3z + tr.y);

    // --- rot path: standardize(conj(root) * glb_rot), 4 quats ---
    #pragma unroll
    for (int k = 0; k < 4; k++) {
        const float4 g = __ldg(glb_rot4 + u * 4 + k);
        float mw = w * g.x - qx * g.y - qy * g.z - qz * g.w;
        float mx = w * g.y + qx * g.x + qy * g.w - qz * g.z;
        float my = w * g.z - qx * g.w + qy * g.x + qz * g.y;
        float mz = w * g.w + qx * g.z - qy * g.y + qz * g.x;
        if (mw < 0.0f) { mw = -mw; mx = -mx; my = -my; mz = -mz; }
        rot_out4[u * 4 + k] = make_float4(mw, mx, my, mz);
    }
}

extern "C" void kernel_launch(void* const* d_in, const int* in_sizes, int n_in,
                              void* d_out, int out_size)
{
    const float* glb_pos  = (const float*)d_in[0];  // [B,T,J,3]
    const float* glb_rot  = (const float*)d_in[1];  // [B,T,J,4]
    const float* glb_vel  = (const float*)d_in[2];  // [B,T-1,J,3]
    const float* root_rot = (const float*)d_in[3];  // [B,T,1,4]

    float* pos_out = (float*)d_out;                                  // [B,T,J,3]
    float* rot_out = (float*)d_out + (size_t)B_ * T_ * J_ * 3;       // [B,T,J,4]

    traj_kernel<<<B_, T_>>>(glb_pos, glb_vel, root_rot);

    const size_t NU = (size_t)B_ * T_ * J_ / 4;   // 524288 threads
    const int threads = 256;
    const int blocks = (int)((NU + threads - 1) / threads);
    apply_kernel<<<blocks, threads>>>(
        reinterpret_cast<const float4*>(glb_pos),
        reinterpret_cast<const float4*>(glb_rot),
        reinterpret_cast<const float4*>(root_rot),
        reinterpret_cast<float4*>(pos_out),
        reinterpret_cast<float4*>(rot_out));
}

// round 15
// speedup vs baseline: 1.1454x; 1.1454x over previous
#include <cuda_runtime.h>

// B=64, T=1024, J=32 (fixed by the reference's setup_inputs)
#define B_ 64
#define T_ 1024
#define J_ 32

// Scratch: per-(b,t) root trajectory (x,z only) — 64*1024 float2 = 512 KB
__device__ float2 d_traj[B_ * T_];

// Rotate point p by quaternion (w, x, y, z): p' = p + 2w(v x p) + 2 v x (v x p)
__device__ __forceinline__ void quat_rotate(
    float w, float x, float y, float z,
    float px, float py, float pz,
    float& rx, float& ry, float& rz)
{
    float tx = 2.0f * (y * pz - z * py);
    float ty = 2.0f * (z * px - x * pz);
    float tz = 2.0f * (x * py - y * px);
    rx = px + w * tx + (y * tz - z * ty);
    ry = py + w * ty + (z * tx - x * tz);
    rz = pz + w * tz + (x * ty - y * tx);
}

// One block per batch b; 1024 threads = T time steps.
__global__ void traj_kernel(const float* __restrict__ glb_pos,
                            const float* __restrict__ glb_vel,
                            const float* __restrict__ root_rot)
{
    const int b = blockIdx.x;
    const int t = threadIdx.x;

    // conj(root[b,t])
    const float4 q4 = __ldg(reinterpret_cast<const float4*>(root_rot) + (size_t)b * T_ + t);
    const float w = q4.x, qx = -q4.y, qy = -q4.z, qz = -q4.w;

    // vel_rot[b,t,0] (x,z) for t < T-1
    float ex = 0.0f, ez = 0.0f;
    if (t < T_ - 1) {
        // joint-0 velocity: 12 bytes at a 384-byte stride, 16B-aligned, and
        // 31 joints of data follow it -> a 16B vector load is safe & in-bounds.
        const size_t fidx = (((size_t)b * (T_ - 1) + t) * J_) * 3;
        const float4 v4 = __ldg(reinterpret_cast<const float4*>(glb_vel + fidx));
        float rx, ry, rz;
        quat_rotate(w, qx, qy, qz, v4.x, v4.y, v4.z, rx, ry, rz);
        ex = rx; ez = rz;
    }

    // --- exclusive block scan of (ex, ez) over the 1024 threads ---
    const int lane = t & 31, warp = t >> 5;
    float ix = ex, iz = ez;  // warp-inclusive
    #pragma unroll
    for (int o = 1; o < 32; o <<= 1) {
        float sx = __shfl_up_sync(0xFFFFFFFFu, ix, o);
        float sz = __shfl_up_sync(0xFFFFFFFFu, iz, o);
        if (lane >= o) { ix += sx; iz += sz; }
    }

    __shared__ float wsx[32], wsz[32];
    __shared__ float2 base_sh;
    if (lane == 31) { wsx[warp] = ix; wsz[warp] = iz; }

    if (t == 0) {
        // base = rotate(conj(root[b,0]), glb_pos[b,0,0]); thread 0 holds root[b,0]
        const float4 p4 = __ldg(reinterpret_cast<const float4*>(glb_pos + (size_t)b * T_ * J_ * 3));
        float bx, by, bz;
        quat_rotate(w, qx, qy, qz, p4.x, p4.y, p4.z, bx, by, bz);
        base_sh = make_float2(bx, bz);
    }
    __syncthreads();

    if (warp == 0) {
        float sx = wsx[lane], sz = wsz[lane];
        #pragma unroll
        for (int o = 1; o < 32; o <<= 1) {
            float ax = __shfl_up_sync(0xFFFFFFFFu, sx, o);
            float az = __shfl_up_sync(0xFFFFFFFFu, sz, o);
            if (lane >= o) { sx += ax; sz += az; }
        }
        wsx[lane] = sx; wsz[lane] = sz;
    }
    __syncthreads();

    float prefx = (ix - ex) + (warp > 0 ? wsx[warp - 1] : 0.0f);
    float prefz = (iz - ez) + (warp > 0 ? wsz[warp - 1] : 0.0f);

    d_traj[(size_t)b * T_ + t] = make_float2(base_sh.x + prefx, base_sh.y + prefz);
}

// One thread handles TWO independent points: u and u + N/2.
// ALL loads are issued before ANY compute, so the SASS front-batches ~8 LDGs
// per thread -> high MLP in flight per warp, while thread count stays at 1M
// (vs 2M thread-per-point). Coalescing is identical to thread-per-point in
// each half; each warp shares one (b,t) per half so root/traj loads broadcast.
__global__ void apply_kernel(const float* __restrict__ glb_pos,
                             const float4* __restrict__ glb_rot4,
                             const float4* __restrict__ root_rot4,
                             float* __restrict__ pos_out,
                             float4* __restrict__ rot_out4)
{
    const size_t N = (size_t)B_ * T_ * J_;
    const size_t H = N / 2;
    const size_t u = (size_t)blockIdx.x * blockDim.x + threadIdx.x;
    if (u >= H) return;

    const size_t i0 = u, i1 = u + H;
    const size_t bt0 = i0 >> 5, bt1 = i1 >> 5;

    // ---------------- load phase (everything, no compute) ----------------
    const float4 q0 = __ldg(root_rot4 + bt0);
    const float4 q1 = __ldg(root_rot4 + bt1);

    const float* p0 = glb_pos + i0 * 3;
    const float* p1 = glb_pos + i1 * 3;
    const float p0x = p0[0], p0y = p0[1], p0z = p0[2];
    const float p1x = p1[0], p1y = p1[1], p1z = p1[2];

    const float4 g0 = __ldg(glb_rot4 + i0);
    const float4 g1 = __ldg(glb_rot4 + i1);

    const float2 tr0 = __ldg(&d_traj[bt0]);
    const float2 tr1 = __ldg(&d_traj[bt1]);

    // ---------------- compute + store: point 0 ----------------
    {
        const float w = q0.x, qx = -q0.y, qy = -q0.z, qz = -q0.w;

        float rx, ry, rz;
        quat_rotate(w, qx, qy, qz, p0x, p0y, p0z, rx, ry, rz);
        float* po = pos_out + i0 * 3;
        po[0] = rx + tr0.x;
        po[1] = ry;
        po[2] = rz + tr0.y;

        float mw = w * g0.x - qx * g0.y - qy * g0.z - qz * g0.w;
        float mx = w * g0.y + qx * g0.x + qy * g0.w - qz * g0.z;
        float my = w * g0.z - qx * g0.w + qy * g0.x + qz * g0.y;
        float mz = w * g0.w + qx * g0.z - qy * g0.y + qz * g0.x;
        if (mw < 0.0f) { mw = -mw; mx = -mx; my = -my; mz = -mz; }
        rot_out4[i0] = make_float4(mw, mx, my, mz);
    }

    // ---------------- compute + store: point 1 ----------------
    {
        const float w = q1.x, qx = -q1.y, qy = -q1.z, qz = -q1.w;

        float rx, ry, rz;
        quat_rotate(w, qx, qy, qz, p1x, p1y, p1z, rx, ry, rz);
        float* po = pos_out + i1 * 3;
        po[0] = rx + tr1.x;
        po[1] = ry;
        po[2] = rz + tr1.y;

        float mw = w * g1.x - qx * g1.y - qy * g1.z - qz * g1.w;
        float mx = w * g1.y + qx * g1.x + qy * g1.w - qz * g1.z;
        float my = w * g1.z - qx * g1.w + qy * g1.x + qz * g1.y;
        float mz = w * g1.w + qx * g1.z - qy * g1.y + qz * g1.x;
        if (mw < 0.0f) { mw = -mw; mx = -mx; my = -my; mz = -mz; }
        rot_out4[i1] = make_float4(mw, mx, my, mz);
    }
}

extern "C" void kernel_launch(void* const* d_in, const int* in_sizes, int n_in,
                              void* d_out, int out_size)
{
    const float* glb_pos  = (const float*)d_in[0];  // [B,T,J,3]
    const float* glb_rot  = (const float*)d_in[1];  // [B,T,J,4]
    const float* glb_vel  = (const float*)d_in[2];  // [B,T-1,J,3]
    const float* root_rot = (const float*)d_in[3];  // [B,T,1,4]

    float* pos_out = (float*)d_out;                                  // [B,T,J,3]
    float* rot_out = (float*)d_out + (size_t)B_ * T_ * J_ * 3;       // [B,T,J,4]

    traj_kernel<<<B_, T_>>>(glb_pos, glb_vel, root_rot);

    const size_t H = (size_t)B_ * T_ * J_ / 2;   // 1,048,576 threads
    const int threads = 256;
    const int blocks = (int)((H + threads - 1) / threads);
    apply_kernel<<<blocks, threads>>>(
        glb_pos,
        reinterpret_cast<const float4*>(glb_rot),
        reinterpret_cast<const float4*>(root_rot),
        pos_out,
        reinterpret_cast<float4*>(rot_out));
}